// round 5
// baseline (speedup 1.0000x reference)
#include <cuda_runtime.h>
#include <cstdint>

#define NBATCH 2
#define CIN    512
#define HCH    256
#define NPIX   6272      // 8*28*28
#define QB     32
#define KB     64
#define QSCALE 16.0f     // sqrt(256)

typedef unsigned long long u64;

// ---------------- device scratch (no allocations allowed) ----------------
__device__ float g_theta[NBATCH * NPIX * HCH];  // Q rows: [b][m][o]
__device__ float g_phiT [NBATCH * HCH * NPIX];  // K transposed: [b][o][m]
__device__ float g_v    [NBATCH * NPIX * HCH];  // V rows: [b][m][o]
__device__ float g_y    [NBATCH * NPIX * HCH];  // attention out: [b][m][o]

// ---------------- f32x2 packed helpers (sm_100+) ----------------
__device__ __forceinline__ u64 pack2(float lo, float hi) {
    u64 r; asm("mov.b64 %0, {%1, %2};" : "=l"(r) : "f"(lo), "f"(hi)); return r;
}
__device__ __forceinline__ void unpack2(u64 v, float& lo, float& hi) {
    asm("mov.b64 {%0, %1}, %2;" : "=f"(lo), "=f"(hi) : "l"(v));
}
__device__ __forceinline__ void fma2(u64& d, u64 a, u64 b) {
    asm("fma.rn.f32x2 %0, %1, %2, %0;" : "+l"(d) : "l"(a), "l"(b));
}
__device__ __forceinline__ void mul2(u64& d, u64 a) {
    asm("mul.rn.f32x2 %0, %0, %1;" : "+l"(d) : "l"(a));
}

// =====================================================================
// Kernel 1: input projections.  C[o][m] = sum_c W[o][c] * X[b][c][m]
// z = b*3 + ws;  ws: 0 -> theta (store [m][o]), 1 -> phi (store [o][m]),
//                2 -> g (store [m][o])
// 64x64 output tile, K-tile 32, f32x2 pair-partial accumulators.
// =====================================================================
__global__ __launch_bounds__(256, 2) void proj_kernel(
    const float* __restrict__ x,
    const float* __restrict__ w_g,
    const float* __restrict__ w_theta,
    const float* __restrict__ w_phi)
{
    __shared__ float As[64 * 36];   // [o-row][c-chunk 32 + pad4]
    __shared__ float Bs[64 * 36];   // [m-row][c-chunk 32 + pad4] (transposed X)

    const int t  = threadIdx.x;
    const int b  = blockIdx.z / 3;
    const int ws = blockIdx.z % 3;
    const float* W = (ws == 0) ? w_theta : (ws == 1) ? w_phi : w_g;
    const int o0 = blockIdx.y * 64;
    const int m0 = blockIdx.x * 64;
    const float* xb = x + (size_t)b * CIN * NPIX;

    const int a  = t >> 4;   // 0..15 over o
    const int bb = t & 15;   // 0..15 over m

    u64 acc2[4][4];
    #pragma unroll
    for (int i = 0; i < 4; ++i)
        #pragma unroll
        for (int j = 0; j < 4; ++j) acc2[i][j] = 0ull;

    for (int c0 = 0; c0 < CIN; c0 += 32) {
        __syncthreads();
        // A tile: W[o0..+64][c0..+32], direct
        #pragma unroll
        for (int i = t; i < 512; i += 256) {
            int r = i >> 3, c4 = i & 7;
            *(float4*)(As + r * 36 + c4 * 4) =
                *(const float4*)(W + (size_t)(o0 + r) * CIN + c0 + c4 * 4);
        }
        // B tile: X[c0..+32][m0..+64], transposed into [m][c]
        #pragma unroll
        for (int i = t; i < 512; i += 256) {
            int c = i >> 4, m4 = i & 15;
            float4 v = *(const float4*)(xb + (size_t)(c0 + c) * NPIX + m0 + m4 * 4);
            Bs[(m4 * 4 + 0) * 36 + c] = v.x;
            Bs[(m4 * 4 + 1) * 36 + c] = v.y;
            Bs[(m4 * 4 + 2) * 36 + c] = v.z;
            Bs[(m4 * 4 + 3) * 36 + c] = v.w;
        }
        __syncthreads();

        #pragma unroll
        for (int c4 = 0; c4 < 8; ++c4) {
            ulonglong2 ar[4], br[4];
            #pragma unroll
            for (int i = 0; i < 4; ++i)
                ar[i] = *(const ulonglong2*)(As + (a * 4 + i) * 36 + c4 * 4);
            #pragma unroll
            for (int j = 0; j < 4; ++j)
                br[j] = *(const ulonglong2*)(Bs + (bb * 4 + j) * 36 + c4 * 4);
            #pragma unroll
            for (int i = 0; i < 4; ++i)
                #pragma unroll
                for (int j = 0; j < 4; ++j) {
                    fma2(acc2[i][j], ar[i].x, br[j].x);
                    fma2(acc2[i][j], ar[i].y, br[j].y);
                }
        }
    }

    float acc[4][4];
    #pragma unroll
    for (int i = 0; i < 4; ++i)
        #pragma unroll
        for (int j = 0; j < 4; ++j) {
            float lo, hi; unpack2(acc2[i][j], lo, hi);
            acc[i][j] = lo + hi;
        }

    if (ws == 1) {  // phi -> [b][o][m]
        float* out = g_phiT + (size_t)b * HCH * NPIX;
        #pragma unroll
        for (int i = 0; i < 4; ++i) {
            float4 v = make_float4(acc[i][0], acc[i][1], acc[i][2], acc[i][3]);
            *(float4*)(out + (size_t)(o0 + a * 4 + i) * NPIX + m0 + bb * 4) = v;
        }
    } else {        // theta / g -> [b][m][o]
        float* out = ((ws == 0) ? g_theta : g_v) + (size_t)b * NPIX * HCH;
        #pragma unroll
        for (int j = 0; j < 4; ++j) {
            float4 v = make_float4(acc[0][j], acc[1][j], acc[2][j], acc[3][j]);
            *(float4*)(out + (size_t)(m0 + bb * 4 + j) * HCH + o0 + a * 4) = v;
        }
    }
}

// =====================================================================
// Kernel 2: flash attention.  Per (q-block of 32 rows, batch).
//   S = 16 * Q K^T  (64 keys/block), online softmax, O += P V.
// 256 threads.
// Phase A mapping: thread = (rg = lane&7, cg = warp*4 + lane>>3)
//   -> rows {4rg..4rg+3}, cols {2cg, 2cg+1}.
//   Q via one LDS.128 (1 wavefront/warp), K via one LDS.64 (1 wf/warp).
// Phase C mapping: (ty = t/64 -> 8 rows, tx = t%64 -> 4 consecutive d).
// f32x2 throughout the MAC loops.
// =====================================================================
#define ATT_SMEM ((HCH*QB + HCH*KB + KB*HCH + QB*68 + 3*QB) * 4)

__global__ __launch_bounds__(256, 1) void attn_kernel()
{
    extern __shared__ float sm[];
    float* Qp  = sm;                    // [256 d][32 r]
    float* Kt  = Qp + HCH * QB;         // [256 d][64 j]
    float* Vs  = Kt + HCH * KB;         // [64 j][256 d]
    float* Ps  = Vs + KB * HCH;         // [32 r][68]
    float* m_s = Ps + QB * 68;          // [32]
    float* l_s = m_s + QB;              // [32]
    float* al_s = l_s + QB;             // [32]

    const int t  = threadIdx.x;
    const int b  = blockIdx.y;
    const int q0 = blockIdx.x * QB;
    const int tx = t & 63;
    const int ty = t >> 6;
    // Phase A thread tile: 4 rows x 2 cols
    const int rg = t & 7;                       // row group: rows 4*rg..4*rg+3
    const int cg = (t >> 5) * 4 + ((t & 31) >> 3);  // col group: cols 2*cg, 2*cg+1

    const float* th = g_theta + (size_t)b * NPIX * HCH;
    const float* ph = g_phiT  + (size_t)b * HCH * NPIX;
    const float* gv = g_v     + (size_t)b * NPIX * HCH;

    // Q tile, pre-scaled by 16, stored transposed: Qp[d*32 + r]
    for (int i = t; i < QB * HCH / 4; i += 256) {   // 2048 float4
        int r = i >> 6, d4 = i & 63;
        float4 v = *(const float4*)(th + (size_t)(q0 + r) * HCH + d4 * 4);
        Qp[(d4 * 4 + 0) * QB + r] = QSCALE * v.x;
        Qp[(d4 * 4 + 1) * QB + r] = QSCALE * v.y;
        Qp[(d4 * 4 + 2) * QB + r] = QSCALE * v.z;
        Qp[(d4 * 4 + 3) * QB + r] = QSCALE * v.w;
    }
    if (t < QB) { m_s[t] = -INFINITY; l_s[t] = 0.0f; }

    u64 o2[8][2];
    #pragma unroll
    for (int i = 0; i < 8; ++i) { o2[i][0] = 0ull; o2[i][1] = 0ull; }

    for (int kb = 0; kb < NPIX / KB; ++kb) {
        const int k0 = kb * KB;
        __syncthreads();
        // K tile (already transposed in global): Kt[d][j]
        for (int i = t; i < HCH * KB / 4; i += 256) {   // 4096 float4
            int d = i >> 4, j4 = i & 15;
            *(float4*)(Kt + d * KB + j4 * 4) =
                *(const float4*)(ph + (size_t)d * NPIX + k0 + j4 * 4);
        }
        // V tile: Vs[j][d]
        for (int i = t; i < KB * HCH / 4; i += 256) {
            int j = i >> 6, d4 = i & 63;
            *(float4*)(Vs + j * HCH + d4 * 4) =
                *(const float4*)(gv + (size_t)(k0 + j) * HCH + d4 * 4);
        }
        __syncthreads();

        // ---- Phase A: S = Q K^T. acc[c][rp] = rows (4rg+2rp, 4rg+2rp+1),
        //      col 2cg+c, packed over the row pair. ----
        u64 s2[2][2] = {{0ull, 0ull}, {0ull, 0ull}};
        #pragma unroll 4
        for (int d = 0; d < HCH; ++d) {
            // Q: 4 consecutive rows -> 2 natural row-pair packs
            ulonglong2 qq = *(const ulonglong2*)(Qp + d * QB + rg * 4);
            // K: 2 consecutive cols
            u64 kk = *(const u64*)(Kt + d * KB + cg * 2);
            float k0f, k1f; unpack2(kk, k0f, k1f);
            u64 k2a = pack2(k0f, k0f);
            u64 k2b = pack2(k1f, k1f);
            fma2(s2[0][0], qq.x, k2a);
            fma2(s2[0][1], qq.y, k2a);
            fma2(s2[1][0], qq.x, k2b);
            fma2(s2[1][1], qq.y, k2b);
        }
        #pragma unroll
        for (int c = 0; c < 2; ++c)
            #pragma unroll
            for (int rp = 0; rp < 2; ++rp) {
                float sa, sb; unpack2(s2[c][rp], sa, sb);
                Ps[(rg * 4 + rp * 2)     * 68 + cg * 2 + c] = sa;
                Ps[(rg * 4 + rp * 2 + 1) * 68 + cg * 2 + c] = sb;
            }
        __syncthreads();

        // ---- Phase B: online softmax (8 warps x 4 rows) ----
        {
            const int w = t >> 5, l = t & 31;
            #pragma unroll
            for (int rr = 0; rr < 4; ++rr) {
                int r = w * 4 + rr;
                float s0 = Ps[r * 68 + l];
                float s1 = Ps[r * 68 + 32 + l];
                float mx = fmaxf(s0, s1);
                #pragma unroll
                for (int o = 16; o; o >>= 1) mx = fmaxf(mx, __shfl_xor_sync(~0u, mx, o));
                float mold = m_s[r];
                float mnew = fmaxf(mold, mx);
                float p0 = __expf(s0 - mnew);
                float p1 = __expf(s1 - mnew);
                float sum = p0 + p1;
                #pragma unroll
                for (int o = 16; o; o >>= 1) sum += __shfl_xor_sync(~0u, sum, o);
                Ps[r * 68 + l]      = p0;
                Ps[r * 68 + 32 + l] = p1;
                if (l == 0) {
                    float al = __expf(mold - mnew);
                    al_s[r] = al;
                    l_s[r]  = l_s[r] * al + sum;
                    m_s[r]  = mnew;
                }
            }
        }
        __syncthreads();

        // ---- Phase C: rescale O, accumulate P V ----
        #pragma unroll
        for (int i = 0; i < 8; ++i) {
            float al = al_s[ty * 8 + i];
            u64 a2 = pack2(al, al);
            mul2(o2[i][0], a2);
            mul2(o2[i][1], a2);
        }
        for (int j4 = 0; j4 < KB / 4; ++j4) {
            ulonglong2 v2[4];
            #pragma unroll
            for (int kk = 0; kk < 4; ++kk)
                v2[kk] = *(const ulonglong2*)(Vs + (j4 * 4 + kk) * HCH + tx * 4);
            #pragma unroll
            for (int i = 0; i < 8; ++i) {
                float4 p4 = *(const float4*)(Ps + (ty * 8 + i) * 68 + j4 * 4);
                u64 pa = pack2(p4.x, p4.x);
                u64 pb = pack2(p4.y, p4.y);
                u64 pc = pack2(p4.z, p4.z);
                u64 pd = pack2(p4.w, p4.w);
                fma2(o2[i][0], v2[0].x, pa); fma2(o2[i][1], v2[0].y, pa);
                fma2(o2[i][0], v2[1].x, pb); fma2(o2[i][1], v2[1].y, pb);
                fma2(o2[i][0], v2[2].x, pc); fma2(o2[i][1], v2[2].y, pc);
                fma2(o2[i][0], v2[3].x, pd); fma2(o2[i][1], v2[3].y, pd);
            }
        }
    }

    // ---- epilogue: normalize and write y[b][m][o] ----
    float* yb = g_y + (size_t)b * NPIX * HCH;
    #pragma unroll
    for (int i = 0; i < 8; ++i) {
        int r = ty * 8 + i;
        float inv = 1.0f / l_s[r];
        float4 o;
        unpack2(o2[i][0], o.x, o.y);
        unpack2(o2[i][1], o.z, o.w);
        o.x *= inv; o.y *= inv; o.z *= inv; o.w *= inv;
        *(float4*)(yb + (size_t)(q0 + r) * HCH + tx * 4) = o;
    }
}

// =====================================================================
// Kernel 3: output projection + residual.
//   out[b][c][m] = x[b][c][m] + sum_o Wout[c][o] * y[b][m][o]
// =====================================================================
__global__ __launch_bounds__(256, 2) void outproj_kernel(
    const float* __restrict__ x,
    const float* __restrict__ w_out,
    float* __restrict__ out)
{
    __shared__ float As[64 * 36];   // [c-row][o-chunk 32 + pad]
    __shared__ float Bs[64 * 36];   // [m-row][o-chunk 32 + pad]

    const int t  = threadIdx.x;
    const int b  = blockIdx.z;
    const int c0 = blockIdx.y * 64;
    const int m0 = blockIdx.x * 64;
    const float* yb = g_y + (size_t)b * NPIX * HCH;

    const int a  = t >> 4;   // over c
    const int bb = t & 15;   // over m

    u64 acc2[4][4];
    #pragma unroll
    for (int i = 0; i < 4; ++i)
        #pragma unroll
        for (int j = 0; j < 4; ++j) acc2[i][j] = 0ull;

    for (int o0 = 0; o0 < HCH; o0 += 32) {
        __syncthreads();
        #pragma unroll
        for (int i = t; i < 512; i += 256) {
            int r = i >> 3, o4 = i & 7;
            *(float4*)(As + r * 36 + o4 * 4) =
                *(const float4*)(w_out + (size_t)(c0 + r) * HCH + o0 + o4 * 4);
        }
        #pragma unroll
        for (int i = t; i < 512; i += 256) {
            int r = i >> 3, o4 = i & 7;
            *(float4*)(Bs + r * 36 + o4 * 4) =
                *(const float4*)(yb + (size_t)(m0 + r) * HCH + o0 + o4 * 4);
        }
        __syncthreads();

        #pragma unroll
        for (int o4 = 0; o4 < 8; ++o4) {
            ulonglong2 ar[4], br[4];
            #pragma unroll
            for (int i = 0; i < 4; ++i)
                ar[i] = *(const ulonglong2*)(As + (a * 4 + i) * 36 + o4 * 4);
            #pragma unroll
            for (int j = 0; j < 4; ++j)
                br[j] = *(const ulonglong2*)(Bs + (bb * 4 + j) * 36 + o4 * 4);
            #pragma unroll
            for (int i = 0; i < 4; ++i)
                #pragma unroll
                for (int j = 0; j < 4; ++j) {
                    fma2(acc2[i][j], ar[i].x, br[j].x);
                    fma2(acc2[i][j], ar[i].y, br[j].y);
                }
        }
    }

    #pragma unroll
    for (int i = 0; i < 4; ++i) {
        const int c = c0 + a * 4 + i;
        const size_t base = ((size_t)b * CIN + c) * NPIX + m0 + bb * 4;
        float4 xr = *(const float4*)(x + base);
        float r0, h0, r1, h1, r2, h2, r3, h3;
        unpack2(acc2[i][0], r0, h0);
        unpack2(acc2[i][1], r1, h1);
        unpack2(acc2[i][2], r2, h2);
        unpack2(acc2[i][3], r3, h3);
        float4 v = make_float4(xr.x + r0 + h0, xr.y + r1 + h1,
                               xr.z + r2 + h2, xr.w + r3 + h3);
        *(float4*)(out + base) = v;
    }
}

// =====================================================================
extern "C" void kernel_launch(void* const* d_in, const int* in_sizes, int n_in,
                              void* d_out, int out_size)
{
    const float* x       = (const float*)d_in[0];
    const float* w_g     = (const float*)d_in[1];
    const float* w_theta = (const float*)d_in[2];
    const float* w_phi   = (const float*)d_in[3];
    const float* w_out   = (const float*)d_in[4];
    float* out = (float*)d_out;

    cudaFuncSetAttribute(attn_kernel,
                         cudaFuncAttributeMaxDynamicSharedMemorySize, ATT_SMEM);

    proj_kernel<<<dim3(NPIX / 64, HCH / 64, NBATCH * 3), 256>>>(x, w_g, w_theta, w_phi);
    attn_kernel<<<dim3(NPIX / QB, NBATCH), 256, ATT_SMEM>>>();
    outproj_kernel<<<dim3(NPIX / 64, CIN / 64, NBATCH), 256>>>(x, w_out, out);
}

// round 10
// speedup vs baseline: 2.2616x; 2.2616x over previous
#include <cuda_runtime.h>
#include <cuda_bf16.h>
#include <mma.h>
#include <cstdint>

using namespace nvcuda;

#define NBATCH 2
#define CIN    512
#define HCH    256
#define NPIX   6272      // 8*28*28, = 49*128 = 98*64
#define QSCALE 16.0f     // sqrt(256), baked into Q

typedef unsigned long long u64;

// ---------------- device scratch (no allocations allowed) ----------------
__device__ __align__(256) __nv_bfloat16 g_qh[NBATCH * NPIX * HCH];   // 16*theta hi  [b][m][o]
__device__ __align__(256) __nv_bfloat16 g_ql[NBATCH * NPIX * HCH];   // 16*theta lo
__device__ __align__(256) __nv_bfloat16 g_kh[NBATCH * NPIX * HCH];   // phi hi       [b][m][o]
__device__ __align__(256) __nv_bfloat16 g_kl[NBATCH * NPIX * HCH];   // phi lo
__device__ __align__(256) __nv_bfloat16 g_vt[NBATCH * HCH * NPIX];   // g transposed [b][o][m]
__device__ __align__(256) float         g_S [(size_t)NBATCH * NPIX * NPIX];  // logits
__device__ __align__(256) __nv_bfloat16 g_P [(size_t)NBATCH * NPIX * NPIX];  // softmax bf16
__device__ __align__(256) float         g_y [NBATCH * NPIX * HCH];   // attn out [b][m][o]

// ---------------- f32x2 packed helpers ----------------
__device__ __forceinline__ u64 pack2(float lo, float hi) {
    u64 r; asm("mov.b64 %0, {%1, %2};" : "=l"(r) : "f"(lo), "f"(hi)); return r;
}
__device__ __forceinline__ void unpack2(u64 v, float& lo, float& hi) {
    asm("mov.b64 {%0, %1}, %2;" : "=f"(lo), "=f"(hi) : "l"(v));
}
__device__ __forceinline__ void fma2(u64& d, u64 a, u64 b) {
    asm("fma.rn.f32x2 %0, %1, %2, %0;" : "+l"(d) : "l"(a), "l"(b));
}

__device__ __forceinline__ void bf16split(float v, __nv_bfloat16& h, __nv_bfloat16& l) {
    h = __float2bfloat16(v);
    l = __float2bfloat16(v - __bfloat162float(h));
}

// =====================================================================
// Kernel 1: input projections.  acc[o][m] = sum_c W[o][c] * X[b][c][m]
// ws: 0 -> Q (16*theta, split bf16, [m][o])
//     1 -> K (phi, split bf16, [m][o])
//     2 -> V (g, bf16, transposed [o][m])
// =====================================================================
__global__ __launch_bounds__(256, 2) void proj_kernel(
    const float* __restrict__ x,
    const float* __restrict__ w_g,
    const float* __restrict__ w_theta,
    const float* __restrict__ w_phi)
{
    __shared__ float As[64 * 36];
    __shared__ float Bs[64 * 36];

    const int t  = threadIdx.x;
    const int b  = blockIdx.z / 3;
    const int ws = blockIdx.z % 3;
    const float* W = (ws == 0) ? w_theta : (ws == 1) ? w_phi : w_g;
    const int o0 = blockIdx.y * 64;
    const int m0 = blockIdx.x * 64;
    const float* xb = x + (size_t)b * CIN * NPIX;

    const int a  = t >> 4;
    const int bb = t & 15;

    u64 acc2[4][4];
    #pragma unroll
    for (int i = 0; i < 4; ++i)
        #pragma unroll
        for (int j = 0; j < 4; ++j) acc2[i][j] = 0ull;

    for (int c0 = 0; c0 < CIN; c0 += 32) {
        __syncthreads();
        #pragma unroll
        for (int i = t; i < 512; i += 256) {
            int r = i >> 3, c4 = i & 7;
            *(float4*)(As + r * 36 + c4 * 4) =
                *(const float4*)(W + (size_t)(o0 + r) * CIN + c0 + c4 * 4);
        }
        #pragma unroll
        for (int i = t; i < 512; i += 256) {
            int c = i >> 4, m4 = i & 15;
            float4 v = *(const float4*)(xb + (size_t)(c0 + c) * NPIX + m0 + m4 * 4);
            Bs[(m4 * 4 + 0) * 36 + c] = v.x;
            Bs[(m4 * 4 + 1) * 36 + c] = v.y;
            Bs[(m4 * 4 + 2) * 36 + c] = v.z;
            Bs[(m4 * 4 + 3) * 36 + c] = v.w;
        }
        __syncthreads();

        #pragma unroll
        for (int c4 = 0; c4 < 8; ++c4) {
            ulonglong2 ar[4], br[4];
            #pragma unroll
            for (int i = 0; i < 4; ++i)
                ar[i] = *(const ulonglong2*)(As + (a * 4 + i) * 36 + c4 * 4);
            #pragma unroll
            for (int j = 0; j < 4; ++j)
                br[j] = *(const ulonglong2*)(Bs + (bb * 4 + j) * 36 + c4 * 4);
            #pragma unroll
            for (int i = 0; i < 4; ++i)
                #pragma unroll
                for (int j = 0; j < 4; ++j) {
                    fma2(acc2[i][j], ar[i].x, br[j].x);
                    fma2(acc2[i][j], ar[i].y, br[j].y);
                }
        }
    }

    float acc[4][4];
    #pragma unroll
    for (int i = 0; i < 4; ++i)
        #pragma unroll
        for (int j = 0; j < 4; ++j) {
            float lo, hi; unpack2(acc2[i][j], lo, hi);
            acc[i][j] = lo + hi;
        }

    if (ws == 2) {  // V -> g_vt[b][o][m] bf16
        __nv_bfloat16* out = g_vt + (size_t)b * HCH * NPIX;
        #pragma unroll
        for (int i = 0; i < 4; ++i) {
            __nv_bfloat162* p = (__nv_bfloat162*)(out + (size_t)(o0 + a * 4 + i) * NPIX + m0 + bb * 4);
            __nv_bfloat162 v01, v23;
            v01.x = __float2bfloat16(acc[i][0]); v01.y = __float2bfloat16(acc[i][1]);
            v23.x = __float2bfloat16(acc[i][2]); v23.y = __float2bfloat16(acc[i][3]);
            p[0] = v01; p[1] = v23;
        }
    } else {        // Q / K -> hi+lo bf16 [b][m][o]
        const float s = (ws == 0) ? QSCALE : 1.0f;
        __nv_bfloat16* oh = ((ws == 0) ? g_qh : g_kh) + (size_t)b * NPIX * HCH;
        __nv_bfloat16* ol = ((ws == 0) ? g_ql : g_kl) + (size_t)b * NPIX * HCH;
        #pragma unroll
        for (int j = 0; j < 4; ++j) {
            size_t base = (size_t)(m0 + bb * 4 + j) * HCH + o0 + a * 4;
            __nv_bfloat16 h[4], l[4];
            #pragma unroll
            for (int i = 0; i < 4; ++i) bf16split(s * acc[i][j], h[i], l[i]);
            __nv_bfloat162 h01, h23, l01, l23;
            h01.x = h[0]; h01.y = h[1]; h23.x = h[2]; h23.y = h[3];
            l01.x = l[0]; l01.y = l[1]; l23.x = l[2]; l23.y = l[3];
            ((__nv_bfloat162*)(oh + base))[0] = h01;
            ((__nv_bfloat162*)(oh + base))[1] = h23;
            ((__nv_bfloat162*)(ol + base))[0] = l01;
            ((__nv_bfloat162*)(ol + base))[1] = l23;
        }
    }
}

// =====================================================================
// Kernel 2: S = (Qh+Ql)(Kh+Kl)^T via wmma bf16 (3 combos, ll dropped).
// CTA: 128x128 S-tile, 256 threads (8 warps, warp tile 64x32).
// K-dim 256 staged in 64-wide smem chunks, stride 80 (32B-aligned rows).
// =====================================================================
#define QK_LD   80
#define QK_SMEM (4 * 128 * QK_LD * 2)

__global__ __launch_bounds__(256, 1) void qk_kernel()
{
    extern __shared__ __align__(128) __nv_bfloat16 smem_qk[];
    __nv_bfloat16* sQH = smem_qk;
    __nv_bfloat16* sQL = sQH + 128 * QK_LD;
    __nv_bfloat16* sKH = sQL + 128 * QK_LD;
    __nv_bfloat16* sKL = sKH + 128 * QK_LD;

    const int t = threadIdx.x;
    const int w = t >> 5;
    const int q0 = blockIdx.x * 128, k0 = blockIdx.y * 128, b = blockIdx.z;
    const int wm = (w & 1) * 64;    // warp M offset
    const int wn = (w >> 1) * 32;   // warp N offset

    const __nv_bfloat16* qh = g_qh + (size_t)b * NPIX * HCH;
    const __nv_bfloat16* ql = g_ql + (size_t)b * NPIX * HCH;
    const __nv_bfloat16* kh = g_kh + (size_t)b * NPIX * HCH;
    const __nv_bfloat16* kl = g_kl + (size_t)b * NPIX * HCH;

    wmma::fragment<wmma::accumulator, 16, 16, 16, float> acc[4][2];
    #pragma unroll
    for (int mi = 0; mi < 4; ++mi)
        #pragma unroll
        for (int ni = 0; ni < 2; ++ni) wmma::fill_fragment(acc[mi][ni], 0.0f);

    for (int c0 = 0; c0 < HCH; c0 += 64) {
        __syncthreads();
        #pragma unroll
        for (int it = 0; it < 4; ++it) {
            int i = t + it * 256;
            int r = i >> 3, c = (i & 7) * 8;
            *(uint4*)(sQH + r * QK_LD + c) = *(const uint4*)(qh + (size_t)(q0 + r) * HCH + c0 + c);
            *(uint4*)(sQL + r * QK_LD + c) = *(const uint4*)(ql + (size_t)(q0 + r) * HCH + c0 + c);
            *(uint4*)(sKH + r * QK_LD + c) = *(const uint4*)(kh + (size_t)(k0 + r) * HCH + c0 + c);
            *(uint4*)(sKL + r * QK_LD + c) = *(const uint4*)(kl + (size_t)(k0 + r) * HCH + c0 + c);
        }
        __syncthreads();

        #pragma unroll
        for (int ks = 0; ks < 4; ++ks) {
            const int kk = ks * 16;
            wmma::fragment<wmma::matrix_b, 16, 16, 16, __nv_bfloat16, wmma::col_major> bH[2], bL[2];
            #pragma unroll
            for (int ni = 0; ni < 2; ++ni) {
                wmma::load_matrix_sync(bH[ni], sKH + (size_t)(wn + ni * 16) * QK_LD + kk, QK_LD);
                wmma::load_matrix_sync(bL[ni], sKL + (size_t)(wn + ni * 16) * QK_LD + kk, QK_LD);
            }
            #pragma unroll
            for (int mi = 0; mi < 4; ++mi) {
                wmma::fragment<wmma::matrix_a, 16, 16, 16, __nv_bfloat16, wmma::row_major> aH, aL;
                wmma::load_matrix_sync(aH, sQH + (size_t)(wm + mi * 16) * QK_LD + kk, QK_LD);
                wmma::load_matrix_sync(aL, sQL + (size_t)(wm + mi * 16) * QK_LD + kk, QK_LD);
                #pragma unroll
                for (int ni = 0; ni < 2; ++ni) {
                    wmma::mma_sync(acc[mi][ni], aH, bH[ni], acc[mi][ni]);
                    wmma::mma_sync(acc[mi][ni], aH, bL[ni], acc[mi][ni]);
                    wmma::mma_sync(acc[mi][ni], aL, bH[ni], acc[mi][ni]);
                }
            }
        }
    }

    float* dst = g_S + ((size_t)b * NPIX + q0) * NPIX + k0;
    #pragma unroll
    for (int mi = 0; mi < 4; ++mi)
        #pragma unroll
        for (int ni = 0; ni < 2; ++ni)
            wmma::store_matrix_sync(dst + (size_t)(wm + mi * 16) * NPIX + wn + ni * 16,
                                    acc[mi][ni], NPIX, wmma::mem_row_major);
}

// =====================================================================
// Kernel 3: row softmax.  One row (6272) per 256-thread block, in regs.
// =====================================================================
__global__ __launch_bounds__(256, 4) void softmax_kernel()
{
    __shared__ float red[8];
    const int t = threadIdx.x, wid = t >> 5, lid = t & 31;
    const size_t row = blockIdx.x;
    const float* s = g_S + row * NPIX;
    __nv_bfloat16* p = g_P + row * NPIX;

    float4 v[7];
    float mx = -1e30f;
    #pragma unroll
    for (int it = 0; it < 7; ++it) {
        int idx = it * 256 + t;
        if (idx < NPIX / 4) {
            v[it] = ((const float4*)s)[idx];
            mx = fmaxf(mx, fmaxf(fmaxf(v[it].x, v[it].y), fmaxf(v[it].z, v[it].w)));
        }
    }
    #pragma unroll
    for (int o = 16; o; o >>= 1) mx = fmaxf(mx, __shfl_xor_sync(~0u, mx, o));
    if (lid == 0) red[wid] = mx;
    __syncthreads();
    if (t == 0) {
        float m = red[0];
        #pragma unroll
        for (int i = 1; i < 8; ++i) m = fmaxf(m, red[i]);
        red[0] = m;
    }
    __syncthreads();
    mx = red[0];
    __syncthreads();

    float sum = 0.0f;
    #pragma unroll
    for (int it = 0; it < 7; ++it) {
        int idx = it * 256 + t;
        if (idx < NPIX / 4) {
            v[it].x = __expf(v[it].x - mx);
            v[it].y = __expf(v[it].y - mx);
            v[it].z = __expf(v[it].z - mx);
            v[it].w = __expf(v[it].w - mx);
            sum += v[it].x + v[it].y + v[it].z + v[it].w;
        }
    }
    #pragma unroll
    for (int o = 16; o; o >>= 1) sum += __shfl_xor_sync(~0u, sum, o);
    if (lid == 0) red[wid] = sum;
    __syncthreads();
    if (t == 0) {
        float l = 0.0f;
        #pragma unroll
        for (int i = 0; i < 8; ++i) l += red[i];
        red[0] = 1.0f / l;
    }
    __syncthreads();
    const float inv = red[0];

    #pragma unroll
    for (int it = 0; it < 7; ++it) {
        int idx = it * 256 + t;
        if (idx < NPIX / 4) {
            __nv_bfloat162 a, c;
            a.x = __float2bfloat16(v[it].x * inv);
            a.y = __float2bfloat16(v[it].y * inv);
            c.x = __float2bfloat16(v[it].z * inv);
            c.y = __float2bfloat16(v[it].w * inv);
            ((__nv_bfloat162*)p)[idx * 2]     = a;
            ((__nv_bfloat162*)p)[idx * 2 + 1] = c;
        }
    }
}

// =====================================================================
// Kernel 4: y = P * V via wmma bf16.
// CTA: [64 m x 128 d], 256 threads (8 warps, warp tile 32x32), K=6272.
// =====================================================================
#define PV_LD 80

__global__ __launch_bounds__(256, 1) void pv_kernel()
{
    __shared__ alignas(128) __nv_bfloat16 sP[64 * PV_LD];
    __shared__ alignas(128) __nv_bfloat16 sV[128 * PV_LD];

    const int t = threadIdx.x;
    const int w = t >> 5;
    const int q0 = blockIdx.x * 64, d0 = blockIdx.y * 128, b = blockIdx.z;
    const int wm = (w & 1) * 32;
    const int wn = (w >> 1) * 32;

    const __nv_bfloat16* P  = g_P + (size_t)b * NPIX * NPIX;
    const __nv_bfloat16* vt = g_vt + (size_t)b * HCH * NPIX;

    wmma::fragment<wmma::accumulator, 16, 16, 16, float> acc[2][2];
    #pragma unroll
    for (int mi = 0; mi < 2; ++mi)
        #pragma unroll
        for (int ni = 0; ni < 2; ++ni) wmma::fill_fragment(acc[mi][ni], 0.0f);

    for (int c0 = 0; c0 < NPIX; c0 += 64) {
        __syncthreads();
        #pragma unroll
        for (int it = 0; it < 2; ++it) {
            int i = t + it * 256;
            int r = i >> 3, c = (i & 7) * 8;
            *(uint4*)(sP + r * PV_LD + c) = *(const uint4*)(P + (size_t)(q0 + r) * NPIX + c0 + c);
        }
        #pragma unroll
        for (int it = 0; it < 4; ++it) {
            int i = t + it * 256;
            int r = i >> 3, c = (i & 7) * 8;
            *(uint4*)(sV + r * PV_LD + c) = *(const uint4*)(vt + (size_t)(d0 + r) * NPIX + c0 + c);
        }
        __syncthreads();

        #pragma unroll
        for (int ks = 0; ks < 4; ++ks) {
            const int kk = ks * 16;
            wmma::fragment<wmma::matrix_b, 16, 16, 16, __nv_bfloat16, wmma::col_major> bV[2];
            #pragma unroll
            for (int ni = 0; ni < 2; ++ni)
                wmma::load_matrix_sync(bV[ni], sV + (size_t)(wn + ni * 16) * PV_LD + kk, PV_LD);
            #pragma unroll
            for (int mi = 0; mi < 2; ++mi) {
                wmma::fragment<wmma::matrix_a, 16, 16, 16, __nv_bfloat16, wmma::row_major> aP;
                wmma::load_matrix_sync(aP, sP + (size_t)(wm + mi * 16) * PV_LD + kk, PV_LD);
                #pragma unroll
                for (int ni = 0; ni < 2; ++ni)
                    wmma::mma_sync(acc[mi][ni], aP, bV[ni], acc[mi][ni]);
            }
        }
    }

    float* dst = g_y + ((size_t)b * NPIX + q0) * HCH + d0;
    #pragma unroll
    for (int mi = 0; mi < 2; ++mi)
        #pragma unroll
        for (int ni = 0; ni < 2; ++ni)
            wmma::store_matrix_sync(dst + (size_t)(wm + mi * 16) * HCH + wn + ni * 16,
                                    acc[mi][ni], HCH, wmma::mem_row_major);
}

// =====================================================================
// Kernel 5: out[b][c][m] = x[b][c][m] + sum_o Wout[c][o] * y[b][m][o]
// =====================================================================
__global__ __launch_bounds__(256, 2) void outproj_kernel(
    const float* __restrict__ x,
    const float* __restrict__ w_out,
    float* __restrict__ out)
{
    __shared__ float As[64 * 36];
    __shared__ float Bs[64 * 36];

    const int t  = threadIdx.x;
    const int b  = blockIdx.z;
    const int c0 = blockIdx.y * 64;
    const int m0 = blockIdx.x * 64;
    const float* yb = g_y + (size_t)b * NPIX * HCH;

    const int a  = t >> 4;
    const int bb = t & 15;

    u64 acc2[4][4];
    #pragma unroll
    for (int i = 0; i < 4; ++i)
        #pragma unroll
        for (int j = 0; j < 4; ++j) acc2[i][j] = 0ull;

    for (int o0 = 0; o0 < HCH; o0 += 32) {
        __syncthreads();
        #pragma unroll
        for (int i = t; i < 512; i += 256) {
            int r = i >> 3, o4 = i & 7;
            *(float4*)(As + r * 36 + o4 * 4) =
                *(const float4*)(w_out + (size_t)(c0 + r) * HCH + o0 + o4 * 4);
        }
        #pragma unroll
        for (int i = t; i < 512; i += 256) {
            int r = i >> 3, o4 = i & 7;
            *(float4*)(Bs + r * 36 + o4 * 4) =
                *(const float4*)(yb + (size_t)(m0 + r) * HCH + o0 + o4 * 4);
        }
        __syncthreads();

        #pragma unroll
        for (int o4 = 0; o4 < 8; ++o4) {
            ulonglong2 ar[4], br[4];
            #pragma unroll
            for (int i = 0; i < 4; ++i)
                ar[i] = *(const ulonglong2*)(As + (a * 4 + i) * 36 + o4 * 4);
            #pragma unroll
            for (int j = 0; j < 4; ++j)
                br[j] = *(const ulonglong2*)(Bs + (bb * 4 + j) * 36 + o4 * 4);
            #pragma unroll
            for (int i = 0; i < 4; ++i)
                #pragma unroll
                for (int j = 0; j < 4; ++j) {
                    fma2(acc2[i][j], ar[i].x, br[j].x);
                    fma2(acc2[i][j], ar[i].y, br[j].y);
                }
        }
    }

    #pragma unroll
    for (int i = 0; i < 4; ++i) {
        const int c = c0 + a * 4 + i;
        const size_t base = ((size_t)b * CIN + c) * NPIX + m0 + bb * 4;
        float4 xr = *(const float4*)(x + base);
        float r0, h0, r1, h1, r2, h2, r3, h3;
        unpack2(acc2[i][0], r0, h0);
        unpack2(acc2[i][1], r1, h1);
        unpack2(acc2[i][2], r2, h2);
        unpack2(acc2[i][3], r3, h3);
        float4 v = make_float4(xr.x + r0 + h0, xr.y + r1 + h1,
                               xr.z + r2 + h2, xr.w + r3 + h3);
        *(float4*)(out + base) = v;
    }
}

// =====================================================================
extern "C" void kernel_launch(void* const* d_in, const int* in_sizes, int n_in,
                              void* d_out, int out_size)
{
    const float* x       = (const float*)d_in[0];
    const float* w_g     = (const float*)d_in[1];
    const float* w_theta = (const float*)d_in[2];
    const float* w_phi   = (const float*)d_in[3];
    const float* w_out   = (const float*)d_in[4];
    float* out = (float*)d_out;

    cudaFuncSetAttribute(qk_kernel, cudaFuncAttributeMaxDynamicSharedMemorySize, QK_SMEM);

    proj_kernel<<<dim3(NPIX / 64, HCH / 64, NBATCH * 3), 256>>>(x, w_g, w_theta, w_phi);
    qk_kernel<<<dim3(NPIX / 128, NPIX / 128, NBATCH), 256, QK_SMEM>>>();
    softmax_kernel<<<NBATCH * NPIX, 256>>>();
    pv_kernel<<<dim3(NPIX / 64, HCH / 128, NBATCH), 256>>>();
    outproj_kernel<<<dim3(NPIX / 64, CIN / 64, NBATCH), 256>>>(x, w_out, out);
}